// round 16
// baseline (speedup 1.0000x reference)
#include <cuda_runtime.h>
#include <cuda_bf16.h>
#include <cuda_fp16.h>
#include <math.h>
#include <stdint.h>

#define BB     2
#define NN     2048
#define DIM    1024
#define HH     16
#define DH     64
#define INNER  1024
#define ROWS   (BB*NN)       // 4096
#define NQKV   3072
#define KD     1024
#define LN_EPS   1e-5f
#define ATTN_EPS 1e-8f
#define SCALE    0.125f
#define SCL2E    0.1803368801111244f   // SCALE * log2(e)

// ---------------------------------------------------------------------------
// Scratch (device globals)
// ---------------------------------------------------------------------------
__device__ __half g_xn[ROWS * DIM];
__device__ __half g_wqT[NQKV * KD];
__device__ __half g_woT[DIM * KD];
__device__ __half g_q[BB*HH*NN*DH];
__device__ __half g_k[BB*HH*NN*DH];
__device__ __half g_v[BB*HH*NN*DH];
__device__ __half g_o[ROWS * INNER];

// ---------------------------------------------------------------------------
// Helpers
// ---------------------------------------------------------------------------
__device__ __forceinline__ uint32_t smem_u32(const void* p) {
    uint32_t a;
    asm("{ .reg .u64 t; cvta.to.shared.u64 t, %1; cvt.u32.u64 %0, t; }" : "=r"(a) : "l"(p));
    return a;
}
#define SWZ128(x) ((x) ^ (((x) >> 3) & 0x70))

__device__ __forceinline__ void cp16(uint32_t dst, const void* src) {
    size_t g = __cvta_generic_to_global(src);
    asm volatile("cp.async.cg.shared.global [%0], [%1], 16;" :: "r"(dst), "l"(g) : "memory");
}
__device__ __forceinline__ void cp_commit() { asm volatile("cp.async.commit_group;" ::: "memory"); }
__device__ __forceinline__ void cp_wait0()  { asm volatile("cp.async.wait_group 0;"  ::: "memory"); }
__device__ __forceinline__ void cp_wait1()  { asm volatile("cp.async.wait_group 1;"  ::: "memory"); }
__device__ __forceinline__ void cp_wait2()  { asm volatile("cp.async.wait_group 2;"  ::: "memory"); }

__device__ __forceinline__ void ldsm4(uint32_t* r, uint32_t a) {
    asm volatile("ldmatrix.sync.aligned.m8n8.x4.shared.b16 {%0,%1,%2,%3}, [%4];"
        : "=r"(r[0]),"=r"(r[1]),"=r"(r[2]),"=r"(r[3]) : "r"(a));
}
__device__ __forceinline__ void ldsm4t(uint32_t* r, uint32_t a) {
    asm volatile("ldmatrix.sync.aligned.m8n8.x4.trans.shared.b16 {%0,%1,%2,%3}, [%4];"
        : "=r"(r[0]),"=r"(r[1]),"=r"(r[2]),"=r"(r[3]) : "r"(a));
}
__device__ __forceinline__ void mma16816h(float* c, const uint32_t* a, const uint32_t* b) {
    asm volatile("mma.sync.aligned.m16n8k16.row.col.f32.f16.f16.f32 "
        "{%0,%1,%2,%3}, {%4,%5,%6,%7}, {%8,%9}, {%0,%1,%2,%3};"
        : "+f"(c[0]),"+f"(c[1]),"+f"(c[2]),"+f"(c[3])
        : "r"(a[0]),"r"(a[1]),"r"(a[2]),"r"(a[3]), "r"(b[0]),"r"(b[1]));
}
__device__ __forceinline__ uint32_t pack2h(float x, float y) {
    __half2 t = __floats2half2_rn(x, y);
    return *(uint32_t*)&t;
}
__device__ __forceinline__ float ex2f(float x) {
    float y; asm("ex2.approx.f32 %0, %1;" : "=f"(y) : "f"(x)); return y;
}

// ---------------------------------------------------------------------------
// LayerNorm -> single fp16
// ---------------------------------------------------------------------------
__global__ void ln_kernel(const float* __restrict__ x,
                          const float* __restrict__ gamma,
                          const float* __restrict__ beta,
                          __half* __restrict__ xn) {
    const int row = blockIdx.x;
    const int t   = threadIdx.x;
    float4 v = ((const float4*)(x + (size_t)row * DIM))[t];
    float s  = v.x + v.y + v.z + v.w;
    float sq = v.x*v.x + v.y*v.y + v.z*v.z + v.w*v.w;
    #pragma unroll
    for (int o = 16; o > 0; o >>= 1) {
        s  += __shfl_down_sync(0xffffffffu, s,  o);
        sq += __shfl_down_sync(0xffffffffu, sq, o);
    }
    __shared__ float ws[8], wq[8], s_mu, s_rstd;
    const int lane = t & 31, wid = t >> 5;
    if (lane == 0) { ws[wid] = s; wq[wid] = sq; }
    __syncthreads();
    if (t == 0) {
        float S = 0.f, Q = 0.f;
        #pragma unroll
        for (int i = 0; i < 8; i++) { S += ws[i]; Q += wq[i]; }
        float mu = S * (1.0f / DIM);
        float var = Q * (1.0f / DIM) - mu * mu;
        s_mu = mu; s_rstd = rsqrtf(var + LN_EPS);
    }
    __syncthreads();
    const float mu = s_mu, rstd = s_rstd;
    float4 g = ((const float4*)gamma)[t];
    float4 b = ((const float4*)beta)[t];
    float y0 = (v.x-mu)*rstd*g.x + b.x, y1 = (v.y-mu)*rstd*g.y + b.y;
    float y2 = (v.z-mu)*rstd*g.z + b.z, y3 = (v.w-mu)*rstd*g.w + b.w;
    __half2* H = (__half2*)(xn + (size_t)row * DIM);
    H[2*t]   = __floats2half2_rn(y0, y1);
    H[2*t+1] = __floats2half2_rn(y2, y3);
}

// ---------------------------------------------------------------------------
// W[K][N] f32 -> WT [N][K] single fp16
// ---------------------------------------------------------------------------
__global__ void transpose_kernel(const float* __restrict__ W,
                                 __half* __restrict__ Th,
                                 int Kd, int Nd) {
    __shared__ float t[32][33];
    const int n0 = blockIdx.x * 32, k0 = blockIdx.y * 32;
    const int tx = threadIdx.x, ty = threadIdx.y;
    #pragma unroll
    for (int i = 0; i < 32; i += 8)
        t[ty + i][tx] = W[(size_t)(k0 + ty + i) * Nd + n0 + tx];
    __syncthreads();
    #pragma unroll
    for (int i = 0; i < 32; i += 8) {
        const size_t idx = (size_t)(n0 + ty + i) * Kd + k0 + tx;
        Th[idx] = __float2half_rn(t[tx][ty + i]);
    }
}

// ---------------------------------------------------------------------------
// Single-fp16 GEMM: 128x128 tile, BK=64, 3-STAGE cp.async (depth-2 prefetch),
// 96KB/CTA -> 2 CTAs/SM.
// ---------------------------------------------------------------------------
#define GBK      64
#define GREG_B   16384             // one region: 128 rows x 128B
#define GSTAGE_B (2*GREG_B)        // 32KB: A, B
#define GSTAGES  3
#define GNC      (KD / GBK)        // 16 chunks
#define GEMM_SMEM (GSTAGES*GSTAGE_B)   // 98304

template<int EPI>
__global__ void __launch_bounds__(256, 2)
gemm_mma_kernel(const __half* __restrict__ A, const __half* __restrict__ B,
                __half* __restrict__ qh, __half* __restrict__ kh, __half* __restrict__ vh,
                const float* __restrict__ bias, float* __restrict__ outf) {
    extern __shared__ char smem[];
    const uint32_t sb = smem_u32(smem);
    const int tid = threadIdx.x;
    const int w = tid >> 5, lane = tid & 31;
    const int wm = w >> 2, wn = w & 3;
    const int brow = blockIdx.y * 128;
    const int bcol = blockIdx.x * 128;

    const int lrow = tid >> 3, lc = tid & 7;
    const uint32_t ldst = SWZ128(lrow * 128 + lc * 16);
    const __half* gpA = A + (size_t)(brow + lrow) * KD + lc * 8;
    const __half* gpB = B + (size_t)(bcol + lrow) * KD + lc * 8;

    auto load_chunk = [&](int stage, int ch) {
        const uint32_t bb = sb + stage * GSTAGE_B;
        const size_t ko = (size_t)ch * GBK;
        #pragma unroll
        for (int sub = 0; sub < 4; sub++) {
            const uint32_t d = ldst + sub * 4096;
            const size_t go = (size_t)sub * 32 * KD + ko;
            cp16(bb + d,          gpA + go);
            cp16(bb + GREG_B + d, gpB + go);
        }
    };

    const int grp = lane >> 3, r8 = lane & 7;
    uint32_t aSwz[4], bSwz[2];
    #pragma unroll
    for (int mf = 0; mf < 4; mf++) {
        const int arow = wm*64 + mf*16 + (lane & 15);
        aSwz[mf] = SWZ128(arow * 128) ^ ((lane >> 4) << 4);
    }
    #pragma unroll
    for (int bt = 0; bt < 2; bt++) {
        const int brw = wn*32 + bt*16 + r8 + ((grp & 2) ? 8 : 0);
        bSwz[bt] = SWZ128(brw * 128) ^ ((grp & 1) ? 16 : 0);
    }

    float acc[4][4][4] = {};

    load_chunk(0, 0); cp_commit();
    load_chunk(1, 1); cp_commit();

    int stC = 0, stL = 2;
    for (int ch = 0; ch < GNC; ch++) {
        if (ch + 2 < GNC) load_chunk(stL, ch + 2);
        cp_commit();          // empty groups retire immediately; count stays exact
        cp_wait2();           // chunk ch's group retired
        __syncthreads();
        const uint32_t bb = sb + stC * GSTAGE_B;

        #pragma unroll
        for (int ks = 0; ks < 4; ks++) {
            uint32_t Bf[2][4];
            #pragma unroll
            for (int bt = 0; bt < 2; bt++)
                ldsm4(Bf[bt], bb + GREG_B + (bSwz[bt] ^ (ks * 32)));
            #pragma unroll
            for (int mf = 0; mf < 4; mf++) {
                uint32_t A4[4];
                ldsm4(A4, bb + (aSwz[mf] ^ (ks * 32)));
                #pragma unroll
                for (int nf = 0; nf < 4; nf++)
                    mma16816h(acc[mf][nf], A4, &Bf[nf >> 1][(nf & 1) * 2]);
            }
        }
        __syncthreads();      // stage free for reuse (ch+3)
        stC = (stC + 1 == GSTAGES) ? 0 : stC + 1;
        stL = (stL + 1 == GSTAGES) ? 0 : stL + 1;
    }

    const int t4 = lane >> 2, t2 = (lane & 3) * 2;
    if (EPI == 0) {
        const int part = bcol >> 10;
        __half* dst = (part == 0) ? qh : (part == 1) ? kh : vh;
        #pragma unroll
        for (int mf = 0; mf < 4; mf++) {
            #pragma unroll
            for (int nf = 0; nf < 4; nf++) {
                const int c0 = bcol + wn*32 + nf*8 + t2;
                const int inner = c0 & 1023;
                const int hh_ = inner >> 6, d = inner & 63;
                #pragma unroll
                for (int rr = 0; rr < 2; rr++) {
                    const int m = brow + wm*64 + mf*16 + t4 + rr*8;
                    const int bq = m >> 11, n = m & 2047;
                    const size_t idx = (((size_t)(bq*HH + hh_))*NN + n)*DH + d;
                    *(uint32_t*)(dst + idx) = pack2h(acc[mf][nf][rr*2], acc[mf][nf][rr*2+1]);
                }
            }
        }
    } else {
        #pragma unroll
        for (int mf = 0; mf < 4; mf++) {
            #pragma unroll
            for (int nf = 0; nf < 4; nf++) {
                const int c0 = bcol + wn*32 + nf*8 + t2;
                #pragma unroll
                for (int rr = 0; rr < 2; rr++) {
                    const int m = brow + wm*64 + mf*16 + t4 + rr*8;
                    float2 o2;
                    o2.x = acc[mf][nf][rr*2]   + bias[c0];
                    o2.y = acc[mf][nf][rr*2+1] + bias[c0+1];
                    *(float2*)(outf + (size_t)m * DIM + c0) = o2;
                }
            }
        }
    }
}

// ---------------------------------------------------------------------------
// Attention: FA2-style fp16. 128-KEY tiles (2 x 64-key sub-passes per sync
// window) -> iterations & syncs halve, MMA density per window doubles.
// Stage = K(16KB)+V(16KB) = 32KB, double-buffered = 64KB/CTA, 2 CTAs/SM.
// ---------------------------------------------------------------------------
#define AREG_B    16384              // K or V region: 128 rows x 128B
#define ASTAGE_B  (2*AREG_B)         // 32KB
#define ATTN_SMEM (2*ASTAGE_B)       // 65536

__global__ void __launch_bounds__(256, 2)
attn_mma_kernel(const __half* __restrict__ Q, const __half* __restrict__ K,
                const __half* __restrict__ V, __half* __restrict__ O) {
    extern __shared__ char smem[];
    const uint32_t sb = smem_u32(smem);
    const int tid = threadIdx.x;
    const int w = tid >> 5, lane = tid & 31;
    const int grp = lane >> 3, r8 = lane & 7;
    const int qt = blockIdx.x, hh_ = blockIdx.y, bq = blockIdx.z;
    const size_t hb = ((size_t)(bq*HH + hh_)) * NN * DH;

    const int lrow = tid >> 3, lc = tid & 7;
    const uint32_t ldst = SWZ128(lrow * 128 + lc * 16);

    // ---- Stage Q tile (128 x 64 fp16 = 16KB) transiently in stage 0 ----
    {
        const __half* qs = Q + hb + (size_t)qt*128*DH + lc*8;
        #pragma unroll
        for (int s = 0; s < 4; s++)
            cp16(sb + ldst + s*4096, qs + (size_t)(lrow + s*32) * DH);
        cp_commit(); cp_wait0();
    }
    __syncthreads();
    const int qrow = w*16 + (lane & 15);
    const uint32_t rb = SWZ128(qrow * 128) ^ ((lane >> 4) << 4);
    uint32_t qf[4][4];
    #pragma unroll
    for (int ks = 0; ks < 4; ks++) ldsm4(qf[ks], sb + (rb ^ (ks * 32)));
    __syncthreads();   // Q extracted; stage 0 may be overwritten

    uint32_t kSwz[4];
    #pragma unroll
    for (int p = 0; p < 4; p++) {
        const int brw = p*16 + r8 + ((grp & 2) ? 8 : 0);
        kSwz[p] = SWZ128(brw * 128) ^ ((grp & 1) ? 16 : 0);
    }
    const int vrsub = r8 + ((grp & 1) ? 8 : 0);
    const uint32_t vcoff = (grp & 2) ? 16 : 0;

    const __half* kp = K + hb + (size_t)lrow * DH + lc*8;
    const __half* vp = V + hb + (size_t)lrow * DH + lc*8;

    // 128-key tile loader: 4 sub-blocks of 32 rows per region
    auto load_tile = [&](int stage, int t) {
        const uint32_t bb = sb + stage * ASTAGE_B;
        const size_t tb = (size_t)t * 128 * DH;
        #pragma unroll
        for (int sub = 0; sub < 4; sub++) {
            const uint32_t d = ldst + sub * 4096;
            const size_t go = tb + (size_t)sub * 32 * DH;
            cp16(bb + d,          kp + go);
            cp16(bb + AREG_B + d, vp + go);
        }
    };

    float oacc[8][4] = {};
    float dsum0 = 0.f, dsum1 = 0.f;

    load_tile(0, 0); cp_commit();

    for (int t = 0; t < NN/128; t++) {
        if (t + 1 < NN/128) load_tile((t + 1) & 1, t + 1);
        cp_commit();
        cp_wait1();
        __syncthreads();
        const uint32_t bb = sb + (t & 1) * ASTAGE_B;

        #pragma unroll
        for (int half = 0; half < 2; half++) {
            const uint32_t kb = bb + half * 8192;            // 64 rows * 128B
            const uint32_t vbb = bb + AREG_B + half * 8192;

            // ---- S = Q K^T (64 keys) ----
            float sacc[8][4] = {};
            #pragma unroll
            for (int ks = 0; ks < 4; ks++) {
                #pragma unroll
                for (int p = 0; p < 4; p++) {
                    uint32_t Kf[4];
                    ldsm4(Kf, kb + (kSwz[p] ^ (ks * 32)));
                    mma16816h(sacc[2*p+0], qf[ks], &Kf[0]);
                    mma16816h(sacc[2*p+1], qf[ks], &Kf[2]);
                }
            }

            // ---- O += exp(S) V ----
            #pragma unroll
            for (int j = 0; j < 4; j++) {
                float pA[4], pB[4];
                #pragma unroll
                for (int e = 0; e < 4; e++) pA[e] = ex2f(sacc[2*j][e]   * SCL2E);
                #pragma unroll
                for (int e = 0; e < 4; e++) pB[e] = ex2f(sacc[2*j+1][e] * SCL2E);
                dsum0 += pA[0] + pA[1] + pB[0] + pB[1];
                dsum1 += pA[2] + pA[3] + pB[2] + pB[3];
                uint32_t pf[4];
                pf[0] = pack2h(pA[0], pA[1]);  pf[1] = pack2h(pA[2], pA[3]);
                pf[2] = pack2h(pB[0], pB[1]);  pf[3] = pack2h(pB[2], pB[3]);
                const int vrow = j*16 + vrsub;
                const uint32_t vb = SWZ128(vrow * 128) ^ vcoff;
                #pragma unroll
                for (int p = 0; p < 4; p++) {
                    uint32_t Vf[4];
                    ldsm4t(Vf, vbb + (vb ^ (p * 32)));
                    mma16816h(oacc[2*p+0], pf, &Vf[0]);
                    mma16816h(oacc[2*p+1], pf, &Vf[2]);
                }
            }
        }
        __syncthreads();
    }

    dsum0 += __shfl_xor_sync(0xffffffffu, dsum0, 1);
    dsum0 += __shfl_xor_sync(0xffffffffu, dsum0, 2);
    dsum1 += __shfl_xor_sync(0xffffffffu, dsum1, 1);
    dsum1 += __shfl_xor_sync(0xffffffffu, dsum1, 2);
    const float inv0 = 1.0f / (dsum0 + ATTN_EPS);
    const float inv1 = 1.0f / (dsum1 + ATTN_EPS);

    const int t4 = lane >> 2, t2 = (lane & 3) * 2;
    #pragma unroll
    for (int nf = 0; nf < 8; nf++) {
        const int d = nf*8 + t2;
        const int n0 = qt*128 + w*16 + t4;
        const size_t i0 = ((size_t)(bq*NN + n0)    )*INNER + hh_*DH + d;
        const size_t i1 = ((size_t)(bq*NN + n0 + 8))*INNER + hh_*DH + d;
        *(uint32_t*)(O + i0) = pack2h(oacc[nf][0]*inv0, oacc[nf][1]*inv0);
        *(uint32_t*)(O + i1) = pack2h(oacc[nf][2]*inv1, oacc[nf][3]*inv1);
    }
}

// ---------------------------------------------------------------------------
extern "C" void kernel_launch(void* const* d_in, const int* in_sizes, int n_in,
                              void* d_out, int out_size) {
    const float* x      = (const float*)d_in[0];
    const float* gamma  = (const float*)d_in[1];
    const float* beta   = (const float*)d_in[2];
    const float* w_qkv  = (const float*)d_in[3];
    const float* w_out  = (const float*)d_in[4];
    const float* b_out  = (const float*)d_in[5];
    float* out = (float*)d_out;

    __half *xn,*wq,*wo,*q,*k,*v,*o;
    cudaGetSymbolAddress((void**)&xn, g_xn);
    cudaGetSymbolAddress((void**)&wq, g_wqT);
    cudaGetSymbolAddress((void**)&wo, g_woT);
    cudaGetSymbolAddress((void**)&q,  g_q);
    cudaGetSymbolAddress((void**)&k,  g_k);
    cudaGetSymbolAddress((void**)&v,  g_v);
    cudaGetSymbolAddress((void**)&o,  g_o);

    cudaFuncSetAttribute(gemm_mma_kernel<0>, cudaFuncAttributeMaxDynamicSharedMemorySize, GEMM_SMEM);
    cudaFuncSetAttribute(gemm_mma_kernel<1>, cudaFuncAttributeMaxDynamicSharedMemorySize, GEMM_SMEM);
    cudaFuncSetAttribute(attn_mma_kernel,    cudaFuncAttributeMaxDynamicSharedMemorySize, ATTN_SMEM);

    ln_kernel<<<ROWS, 256>>>(x, gamma, beta, xn);
    transpose_kernel<<<dim3(NQKV/32, KD/32), dim3(32, 8)>>>(w_qkv, wq, KD, NQKV);
    transpose_kernel<<<dim3(DIM/32,  KD/32), dim3(32, 8)>>>(w_out, wo, KD, DIM);
    gemm_mma_kernel<0><<<dim3(NQKV/128, ROWS/128), 256, GEMM_SMEM>>>(
        xn, wq, q, k, v, nullptr, nullptr);
    attn_mma_kernel<<<dim3(NN/128, HH, BB), 256, ATTN_SMEM>>>(q, k, v, o);
    gemm_mma_kernel<1><<<dim3(DIM/128, ROWS/128), 256, GEMM_SMEM>>>(
        o, wo, nullptr, nullptr, nullptr, b_out, out);
}

// round 17
// speedup vs baseline: 1.0287x; 1.0287x over previous
#include <cuda_runtime.h>
#include <cuda_bf16.h>
#include <cuda_fp16.h>
#include <math.h>
#include <stdint.h>

#define BB     2
#define NN     2048
#define DIM    1024
#define HH     16
#define DH     64
#define INNER  1024
#define ROWS   (BB*NN)       // 4096
#define NQKV   3072
#define KD     1024
#define LN_EPS   1e-5f
#define ATTN_EPS 1e-8f
#define SCALE    0.125f
#define SCL2E    0.1803368801111244f   // SCALE * log2(e)

// ---------------------------------------------------------------------------
// Scratch (device globals)
// ---------------------------------------------------------------------------
__device__ __half g_xn[ROWS * DIM];
__device__ __half g_wqT[NQKV * KD];
__device__ __half g_woT[DIM * KD];
__device__ __half g_q[BB*HH*NN*DH];
__device__ __half g_k[BB*HH*NN*DH];
__device__ __half g_v[BB*HH*NN*DH];
__device__ __half g_o[ROWS * INNER];

// ---------------------------------------------------------------------------
// Helpers
// ---------------------------------------------------------------------------
__device__ __forceinline__ uint32_t smem_u32(const void* p) {
    uint32_t a;
    asm("{ .reg .u64 t; cvta.to.shared.u64 t, %1; cvt.u32.u64 %0, t; }" : "=r"(a) : "l"(p));
    return a;
}
#define SWZ128(x) ((x) ^ (((x) >> 3) & 0x70))

__device__ __forceinline__ void cp16(uint32_t dst, const void* src) {
    size_t g = __cvta_generic_to_global(src);
    asm volatile("cp.async.cg.shared.global [%0], [%1], 16;" :: "r"(dst), "l"(g) : "memory");
}
__device__ __forceinline__ void cp_commit() { asm volatile("cp.async.commit_group;" ::: "memory"); }
__device__ __forceinline__ void cp_wait0()  { asm volatile("cp.async.wait_group 0;"  ::: "memory"); }
__device__ __forceinline__ void cp_wait1()  { asm volatile("cp.async.wait_group 1;"  ::: "memory"); }
__device__ __forceinline__ void cp_wait2()  { asm volatile("cp.async.wait_group 2;"  ::: "memory"); }

__device__ __forceinline__ void ldsm4(uint32_t* r, uint32_t a) {
    asm volatile("ldmatrix.sync.aligned.m8n8.x4.shared.b16 {%0,%1,%2,%3}, [%4];"
        : "=r"(r[0]),"=r"(r[1]),"=r"(r[2]),"=r"(r[3]) : "r"(a));
}
__device__ __forceinline__ void ldsm4t(uint32_t* r, uint32_t a) {
    asm volatile("ldmatrix.sync.aligned.m8n8.x4.trans.shared.b16 {%0,%1,%2,%3}, [%4];"
        : "=r"(r[0]),"=r"(r[1]),"=r"(r[2]),"=r"(r[3]) : "r"(a));
}
__device__ __forceinline__ void mma16816h(float* c, const uint32_t* a, const uint32_t* b) {
    asm volatile("mma.sync.aligned.m16n8k16.row.col.f32.f16.f16.f32 "
        "{%0,%1,%2,%3}, {%4,%5,%6,%7}, {%8,%9}, {%0,%1,%2,%3};"
        : "+f"(c[0]),"+f"(c[1]),"+f"(c[2]),"+f"(c[3])
        : "r"(a[0]),"r"(a[1]),"r"(a[2]),"r"(a[3]), "r"(b[0]),"r"(b[1]));
}
__device__ __forceinline__ uint32_t pack2h(float x, float y) {
    __half2 t = __floats2half2_rn(x, y);
    return *(uint32_t*)&t;
}
__device__ __forceinline__ float ex2f(float x) {
    float y; asm("ex2.approx.f32 %0, %1;" : "=f"(y) : "f"(x)); return y;
}

// ---------------------------------------------------------------------------
// Fused prep: one launch covering LayerNorm + both weight transposes.
//   blocks [0, 4096)          : LN row = bid
//   blocks [4096, 7168)       : w_qkv transpose tile (96 x 32 tiles)
//   blocks [7168, 8192)       : w_out transpose tile (32 x 32 tiles)
// All roles use 256 threads.
// ---------------------------------------------------------------------------
#define PREP_LN_BLOCKS  ROWS                    // 4096
#define PREP_WQ_BLOCKS  ((NQKV/32)*(KD/32))     // 3072
#define PREP_WO_BLOCKS  ((DIM/32)*(KD/32))      // 1024
#define PREP_BLOCKS     (PREP_LN_BLOCKS + PREP_WQ_BLOCKS + PREP_WO_BLOCKS)

__global__ void prep_kernel(const float* __restrict__ x,
                            const float* __restrict__ gamma,
                            const float* __restrict__ beta,
                            const float* __restrict__ w_qkv,
                            const float* __restrict__ w_out,
                            __half* __restrict__ xn,
                            __half* __restrict__ wqT,
                            __half* __restrict__ woT) {
    __shared__ float sm[32 * 33];               // transpose tile / LN scratch
    const int bid = blockIdx.x;
    const int t   = threadIdx.x;

    if (bid < PREP_LN_BLOCKS) {
        // ---- LayerNorm row ----
        const int row = bid;
        float4 v = ((const float4*)(x + (size_t)row * DIM))[t];
        float s  = v.x + v.y + v.z + v.w;
        float sq = v.x*v.x + v.y*v.y + v.z*v.z + v.w*v.w;
        #pragma unroll
        for (int o = 16; o > 0; o >>= 1) {
            s  += __shfl_down_sync(0xffffffffu, s,  o);
            sq += __shfl_down_sync(0xffffffffu, sq, o);
        }
        float* ws = sm; float* wq = sm + 8;
        float* stat = sm + 16;                  // [mu, rstd]
        const int lane = t & 31, wid = t >> 5;
        if (lane == 0) { ws[wid] = s; wq[wid] = sq; }
        __syncthreads();
        if (t == 0) {
            float S = 0.f, Q = 0.f;
            #pragma unroll
            for (int i = 0; i < 8; i++) { S += ws[i]; Q += wq[i]; }
            float mu = S * (1.0f / DIM);
            float var = Q * (1.0f / DIM) - mu * mu;
            stat[0] = mu; stat[1] = rsqrtf(var + LN_EPS);
        }
        __syncthreads();
        const float mu = stat[0], rstd = stat[1];
        float4 g = ((const float4*)gamma)[t];
        float4 b = ((const float4*)beta)[t];
        float y0 = (v.x-mu)*rstd*g.x + b.x, y1 = (v.y-mu)*rstd*g.y + b.y;
        float y2 = (v.z-mu)*rstd*g.z + b.z, y3 = (v.w-mu)*rstd*g.w + b.w;
        __half2* H = (__half2*)(xn + (size_t)row * DIM);
        H[2*t]   = __floats2half2_rn(y0, y1);
        H[2*t+1] = __floats2half2_rn(y2, y3);
    } else {
        // ---- weight transpose tile: W[K][N] f32 -> WT[N][K] fp16 ----
        const float* W;  __half* T;  int Nd, tile;
        if (bid < PREP_LN_BLOCKS + PREP_WQ_BLOCKS) {
            W = w_qkv; T = wqT; Nd = NQKV; tile = bid - PREP_LN_BLOCKS;
        } else {
            W = w_out; T = woT; Nd = DIM;  tile = bid - PREP_LN_BLOCKS - PREP_WQ_BLOCKS;
        }
        const int ntiles = Nd / 32;
        const int n0 = (tile % ntiles) * 32, k0 = (tile / ntiles) * 32;
        const int tx = t & 31, ty = t >> 5;
        float (*tt)[33] = (float(*)[33])sm;
        #pragma unroll
        for (int i = 0; i < 32; i += 8)
            tt[ty + i][tx] = W[(size_t)(k0 + ty + i) * Nd + n0 + tx];
        __syncthreads();
        #pragma unroll
        for (int i = 0; i < 32; i += 8) {
            const size_t idx = (size_t)(n0 + ty + i) * KD + k0 + tx;
            T[idx] = __float2half_rn(tt[tx][ty + i]);
        }
    }
}

// ---------------------------------------------------------------------------
// Single-fp16 GEMM: 128x128 tile, BK=64, 3-STAGE cp.async (depth-2 prefetch),
// 96KB/CTA -> 2 CTAs/SM.  (unchanged from R16)
// ---------------------------------------------------------------------------
#define GBK      64
#define GREG_B   16384
#define GSTAGE_B (2*GREG_B)
#define GSTAGES  3
#define GNC      (KD / GBK)
#define GEMM_SMEM (GSTAGES*GSTAGE_B)   // 98304

template<int EPI>
__global__ void __launch_bounds__(256, 2)
gemm_mma_kernel(const __half* __restrict__ A, const __half* __restrict__ B,
                __half* __restrict__ qh, __half* __restrict__ kh, __half* __restrict__ vh,
                const float* __restrict__ bias, float* __restrict__ outf) {
    extern __shared__ char smem[];
    const uint32_t sb = smem_u32(smem);
    const int tid = threadIdx.x;
    const int w = tid >> 5, lane = tid & 31;
    const int wm = w >> 2, wn = w & 3;
    const int brow = blockIdx.y * 128;
    const int bcol = blockIdx.x * 128;

    const int lrow = tid >> 3, lc = tid & 7;
    const uint32_t ldst = SWZ128(lrow * 128 + lc * 16);
    const __half* gpA = A + (size_t)(brow + lrow) * KD + lc * 8;
    const __half* gpB = B + (size_t)(bcol + lrow) * KD + lc * 8;

    auto load_chunk = [&](int stage, int ch) {
        const uint32_t bb = sb + stage * GSTAGE_B;
        const size_t ko = (size_t)ch * GBK;
        #pragma unroll
        for (int sub = 0; sub < 4; sub++) {
            const uint32_t d = ldst + sub * 4096;
            const size_t go = (size_t)sub * 32 * KD + ko;
            cp16(bb + d,          gpA + go);
            cp16(bb + GREG_B + d, gpB + go);
        }
    };

    const int grp = lane >> 3, r8 = lane & 7;
    uint32_t aSwz[4], bSwz[2];
    #pragma unroll
    for (int mf = 0; mf < 4; mf++) {
        const int arow = wm*64 + mf*16 + (lane & 15);
        aSwz[mf] = SWZ128(arow * 128) ^ ((lane >> 4) << 4);
    }
    #pragma unroll
    for (int bt = 0; bt < 2; bt++) {
        const int brw = wn*32 + bt*16 + r8 + ((grp & 2) ? 8 : 0);
        bSwz[bt] = SWZ128(brw * 128) ^ ((grp & 1) ? 16 : 0);
    }

    float acc[4][4][4] = {};

    load_chunk(0, 0); cp_commit();
    load_chunk(1, 1); cp_commit();

    int stC = 0, stL = 2;
    for (int ch = 0; ch < GNC; ch++) {
        if (ch + 2 < GNC) load_chunk(stL, ch + 2);
        cp_commit();
        cp_wait2();
        __syncthreads();
        const uint32_t bb = sb + stC * GSTAGE_B;

        #pragma unroll
        for (int ks = 0; ks < 4; ks++) {
            uint32_t Bf[2][4];
            #pragma unroll
            for (int bt = 0; bt < 2; bt++)
                ldsm4(Bf[bt], bb + GREG_B + (bSwz[bt] ^ (ks * 32)));
            #pragma unroll
            for (int mf = 0; mf < 4; mf++) {
                uint32_t A4[4];
                ldsm4(A4, bb + (aSwz[mf] ^ (ks * 32)));
                #pragma unroll
                for (int nf = 0; nf < 4; nf++)
                    mma16816h(acc[mf][nf], A4, &Bf[nf >> 1][(nf & 1) * 2]);
            }
        }
        __syncthreads();
        stC = (stC + 1 == GSTAGES) ? 0 : stC + 1;
        stL = (stL + 1 == GSTAGES) ? 0 : stL + 1;
    }

    const int t4 = lane >> 2, t2 = (lane & 3) * 2;
    if (EPI == 0) {
        const int part = bcol >> 10;
        __half* dst = (part == 0) ? qh : (part == 1) ? kh : vh;
        #pragma unroll
        for (int mf = 0; mf < 4; mf++) {
            #pragma unroll
            for (int nf = 0; nf < 4; nf++) {
                const int c0 = bcol + wn*32 + nf*8 + t2;
                const int inner = c0 & 1023;
                const int hh_ = inner >> 6, d = inner & 63;
                #pragma unroll
                for (int rr = 0; rr < 2; rr++) {
                    const int m = brow + wm*64 + mf*16 + t4 + rr*8;
                    const int bq = m >> 11, n = m & 2047;
                    const size_t idx = (((size_t)(bq*HH + hh_))*NN + n)*DH + d;
                    *(uint32_t*)(dst + idx) = pack2h(acc[mf][nf][rr*2], acc[mf][nf][rr*2+1]);
                }
            }
        }
    } else {
        #pragma unroll
        for (int mf = 0; mf < 4; mf++) {
            #pragma unroll
            for (int nf = 0; nf < 4; nf++) {
                const int c0 = bcol + wn*32 + nf*8 + t2;
                #pragma unroll
                for (int rr = 0; rr < 2; rr++) {
                    const int m = brow + wm*64 + mf*16 + t4 + rr*8;
                    float2 o2;
                    o2.x = acc[mf][nf][rr*2]   + bias[c0];
                    o2.y = acc[mf][nf][rr*2+1] + bias[c0+1];
                    *(float2*)(outf + (size_t)m * DIM + c0) = o2;
                }
            }
        }
    }
}

// ---------------------------------------------------------------------------
// Attention: FA2-style fp16, 128-key tiles (unchanged from R16).
// ---------------------------------------------------------------------------
#define AREG_B    16384
#define ASTAGE_B  (2*AREG_B)
#define ATTN_SMEM (2*ASTAGE_B)       // 65536

__global__ void __launch_bounds__(256, 2)
attn_mma_kernel(const __half* __restrict__ Q, const __half* __restrict__ K,
                const __half* __restrict__ V, __half* __restrict__ O) {
    extern __shared__ char smem[];
    const uint32_t sb = smem_u32(smem);
    const int tid = threadIdx.x;
    const int w = tid >> 5, lane = tid & 31;
    const int grp = lane >> 3, r8 = lane & 7;
    const int qt = blockIdx.x, hh_ = blockIdx.y, bq = blockIdx.z;
    const size_t hb = ((size_t)(bq*HH + hh_)) * NN * DH;

    const int lrow = tid >> 3, lc = tid & 7;
    const uint32_t ldst = SWZ128(lrow * 128 + lc * 16);

    {
        const __half* qs = Q + hb + (size_t)qt*128*DH + lc*8;
        #pragma unroll
        for (int s = 0; s < 4; s++)
            cp16(sb + ldst + s*4096, qs + (size_t)(lrow + s*32) * DH);
        cp_commit(); cp_wait0();
    }
    __syncthreads();
    const int qrow = w*16 + (lane & 15);
    const uint32_t rb = SWZ128(qrow * 128) ^ ((lane >> 4) << 4);
    uint32_t qf[4][4];
    #pragma unroll
    for (int ks = 0; ks < 4; ks++) ldsm4(qf[ks], sb + (rb ^ (ks * 32)));
    __syncthreads();

    uint32_t kSwz[4];
    #pragma unroll
    for (int p = 0; p < 4; p++) {
        const int brw = p*16 + r8 + ((grp & 2) ? 8 : 0);
        kSwz[p] = SWZ128(brw * 128) ^ ((grp & 1) ? 16 : 0);
    }
    const int vrsub = r8 + ((grp & 1) ? 8 : 0);
    const uint32_t vcoff = (grp & 2) ? 16 : 0;

    const __half* kp = K + hb + (size_t)lrow * DH + lc*8;
    const __half* vp = V + hb + (size_t)lrow * DH + lc*8;

    auto load_tile = [&](int stage, int t) {
        const uint32_t bb = sb + stage * ASTAGE_B;
        const size_t tb = (size_t)t * 128 * DH;
        #pragma unroll
        for (int sub = 0; sub < 4; sub++) {
            const uint32_t d = ldst + sub * 4096;
            const size_t go = tb + (size_t)sub * 32 * DH;
            cp16(bb + d,          kp + go);
            cp16(bb + AREG_B + d, vp + go);
        }
    };

    float oacc[8][4] = {};
    float dsum0 = 0.f, dsum1 = 0.f;

    load_tile(0, 0); cp_commit();

    for (int t = 0; t < NN/128; t++) {
        if (t + 1 < NN/128) load_tile((t + 1) & 1, t + 1);
        cp_commit();
        cp_wait1();
        __syncthreads();
        const uint32_t bb = sb + (t & 1) * ASTAGE_B;

        #pragma unroll
        for (int half = 0; half < 2; half++) {
            const uint32_t kb = bb + half * 8192;
            const uint32_t vbb = bb + AREG_B + half * 8192;

            float sacc[8][4] = {};
            #pragma unroll
            for (int ks = 0; ks < 4; ks++) {
                #pragma unroll
                for (int p = 0; p < 4; p++) {
                    uint32_t Kf[4];
                    ldsm4(Kf, kb + (kSwz[p] ^ (ks * 32)));
                    mma16816h(sacc[2*p+0], qf[ks], &Kf[0]);
                    mma16816h(sacc[2*p+1], qf[ks], &Kf[2]);
                }
            }

            #pragma unroll
            for (int j = 0; j < 4; j++) {
                float pA[4], pB[4];
                #pragma unroll
                for (int e = 0; e < 4; e++) pA[e] = ex2f(sacc[2*j][e]   * SCL2E);
                #pragma unroll
                for (int e = 0; e < 4; e++) pB[e] = ex2f(sacc[2*j+1][e] * SCL2E);
                dsum0 += pA[0] + pA[1] + pB[0] + pB[1];
                dsum1 += pA[2] + pA[3] + pB[2] + pB[3];
                uint32_t pf[4];
                pf[0] = pack2h(pA[0], pA[1]);  pf[1] = pack2h(pA[2], pA[3]);
                pf[2] = pack2h(pB[0], pB[1]);  pf[3] = pack2h(pB[2], pB[3]);
                const int vrow = j*16 + vrsub;
                const uint32_t vb = SWZ128(vrow * 128) ^ vcoff;
                #pragma unroll
                for (int p = 0; p < 4; p++) {
                    uint32_t Vf[4];
                    ldsm4t(Vf, vbb + (vb ^ (p * 32)));
                    mma16816h(oacc[2*p+0], pf, &Vf[0]);
                    mma16816h(oacc[2*p+1], pf, &Vf[2]);
                }
            }
        }
        __syncthreads();
    }

    dsum0 += __shfl_xor_sync(0xffffffffu, dsum0, 1);
    dsum0 += __shfl_xor_sync(0xffffffffu, dsum0, 2);
    dsum1 += __shfl_xor_sync(0xffffffffu, dsum1, 1);
    dsum1 += __shfl_xor_sync(0xffffffffu, dsum1, 2);
    const float inv0 = 1.0f / (dsum0 + ATTN_EPS);
    const float inv1 = 1.0f / (dsum1 + ATTN_EPS);

    const int t4 = lane >> 2, t2 = (lane & 3) * 2;
    #pragma unroll
    for (int nf = 0; nf < 8; nf++) {
        const int d = nf*8 + t2;
        const int n0 = qt*128 + w*16 + t4;
        const size_t i0 = ((size_t)(bq*NN + n0)    )*INNER + hh_*DH + d;
        const size_t i1 = ((size_t)(bq*NN + n0 + 8))*INNER + hh_*DH + d;
        *(uint32_t*)(O + i0) = pack2h(oacc[nf][0]*inv0, oacc[nf][1]*inv0);
        *(uint32_t*)(O + i1) = pack2h(oacc[nf][2]*inv1, oacc[nf][3]*inv1);
    }
}

// ---------------------------------------------------------------------------
extern "C" void kernel_launch(void* const* d_in, const int* in_sizes, int n_in,
                              void* d_out, int out_size) {
    const float* x      = (const float*)d_in[0];
    const float* gamma  = (const float*)d_in[1];
    const float* beta   = (const float*)d_in[2];
    const float* w_qkv  = (const float*)d_in[3];
    const float* w_out  = (const float*)d_in[4];
    const float* b_out  = (const float*)d_in[5];
    float* out = (float*)d_out;

    __half *xn,*wq,*wo,*q,*k,*v,*o;
    cudaGetSymbolAddress((void**)&xn, g_xn);
    cudaGetSymbolAddress((void**)&wq, g_wqT);
    cudaGetSymbolAddress((void**)&wo, g_woT);
    cudaGetSymbolAddress((void**)&q,  g_q);
    cudaGetSymbolAddress((void**)&k,  g_k);
    cudaGetSymbolAddress((void**)&v,  g_v);
    cudaGetSymbolAddress((void**)&o,  g_o);

    cudaFuncSetAttribute(gemm_mma_kernel<0>, cudaFuncAttributeMaxDynamicSharedMemorySize, GEMM_SMEM);
    cudaFuncSetAttribute(gemm_mma_kernel<1>, cudaFuncAttributeMaxDynamicSharedMemorySize, GEMM_SMEM);
    cudaFuncSetAttribute(attn_mma_kernel,    cudaFuncAttributeMaxDynamicSharedMemorySize, ATTN_SMEM);

    prep_kernel<<<PREP_BLOCKS, 256>>>(x, gamma, beta, w_qkv, w_out, xn, wq, wo);
    gemm_mma_kernel<0><<<dim3(NQKV/128, ROWS/128), 256, GEMM_SMEM>>>(
        xn, wq, q, k, v, nullptr, nullptr);
    attn_mma_kernel<<<dim3(NN/128, HH, BB), 256, ATTN_SMEM>>>(q, k, v, o);
    gemm_mma_kernel<1><<<dim3(DIM/128, ROWS/128), 256, GEMM_SMEM>>>(
        o, wo, nullptr, nullptr, nullptr, b_out, out);
}